// round 6
// baseline (speedup 1.0000x reference)
#include <cuda_runtime.h>
#include <cstdint>
#include <cstddef>

// Problem constants (B=4, H=8, N=2048, D=64, c=1)
#define BH   32
#define NSEQ 2048
#define DDIM 64
#define TILE_M 128
#define TILE_N 128

// ---------------------------------------------------------------------------
// Precomputed norms (allocation-free: __device__ globals), interleaved pairs:
//  g_qn2[i] = (||q_i||^2, 2/max(1-||q_i||^2, 1e-3))
//  g_kn2[i] = (||k_i||^2, 1/max(1-||k_i||^2, 1e-3))
// ---------------------------------------------------------------------------
__device__ float2 g_qn2[BH * NSEQ];
__device__ float2 g_kn2[BH * NSEQ];

__global__ void norm_kernel(const float* __restrict__ q, const float* __restrict__ k) {
    int i = blockIdx.x * blockDim.x + threadIdx.x;   // 0 .. BH*NSEQ-1
    const float4* qp = (const float4*)(q + (size_t)i * DDIM);
    const float4* kp = (const float4*)(k + (size_t)i * DDIM);
    float sq = 0.f, sk = 0.f;
    #pragma unroll
    for (int j = 0; j < 16; ++j) {
        float4 a = qp[j];
        sq = fmaf(a.x, a.x, fmaf(a.y, a.y, fmaf(a.z, a.z, fmaf(a.w, a.w, sq))));
        float4 b = kp[j];
        sk = fmaf(b.x, b.x, fmaf(b.y, b.y, fmaf(b.z, b.z, fmaf(b.w, b.w, sk))));
    }
    g_qn2[i] = make_float2(sq, 2.f / fmaxf(1.f - sq, 1e-3f));
    g_kn2[i] = make_float2(sk, 1.f / fmaxf(1.f - sk, 1e-3f));
}

// ---------------------------------------------------------------------------
// Helpers
// ---------------------------------------------------------------------------
__device__ __forceinline__ uint32_t smem_u32(const void* p) {
    uint32_t a;
    asm("{ .reg .u64 t; cvta.to.shared.u64 t, %1; cvt.u32.u64 %0, t; }" : "=r"(a) : "l"(p));
    return a;
}
__device__ __forceinline__ void cp_async16(uint32_t dst, const void* src) {
    asm volatile("cp.async.cg.shared.global [%0], [%1], 16;" :: "r"(dst), "l"(src));
}

__device__ __forceinline__ void mma_tf32_16x8x8(float* d, const uint32_t* a, const uint32_t* b) {
    asm volatile(
        "mma.sync.aligned.m16n8k8.row.col.f32.tf32.tf32.f32 "
        "{%0,%1,%2,%3}, {%4,%5,%6,%7}, {%8,%9}, {%0,%1,%2,%3};"
        : "+f"(d[0]), "+f"(d[1]), "+f"(d[2]), "+f"(d[3])
        : "r"(a[0]), "r"(a[1]), "r"(a[2]), "r"(a[3]), "r"(b[0]), "r"(b[1]));
}

// acosh(1+t) = log(1 + t + sqrt(t^2+2t)); sqrt.approx(0)=0 so t=0 -> 0 exactly.
__device__ __forceinline__ float hyp_dist(float s, float qnkn, float rr) {
    float diff = fmaf(-2.f, s, qnkn);
    float t = fmaxf(diff, 0.f) * rr;
    float u2 = fmaf(t, t, t + t);
    float u;
    asm("sqrt.approx.f32 %0, %1;" : "=f"(u) : "f"(u2));
    return __logf(1.f + t + u);
}

// ---------------------------------------------------------------------------
// Main kernel: 128x128 output tile per CTA, 256 threads = 8 warps (2M x 4N),
// warp tile 64x32 = 4x4 m16n8k8.
//
// SoA fragment smem layout (A, 128x64): subtile (mt=r>>4, s=c>>3) = 128 words
// at (mt*8+s)*128; plane p = (r>>3&1)|((c>>2&1)<<1) (32 words); word-in-plane
// = ((r&7)^(c>>2&7))*4 + (c&3). Producer: one 16B cp.async per float4,
// conflict-free. Consumer: conflict-free LDS.32. B identical (8x8 subtiles,
// 2 planes). Raw fp32 bits used as tf32 operands (hw truncation).
//
// Staged epilogue: frag smem (64KB) is reused to stage the final hyp values
// (swizzle col ^ ((row&7)<<3)), then copied out with one full row per warp
// instruction (STG.128, 4 lines / 512B = optimal).
//
// Dynamic smem:
//   [0:32768)       afrag 8192 u32   } reused as 64KB stage
//   [32768:65536)   bfrag 8192 u32   }
//   [65536:66560)   qn2s 128 float2
//   [66560:67584)   cn2s 128 float2
// ---------------------------------------------------------------------------
#define SM_AFRAG 0
#define SM_BFRAG 32768
#define SM_QN    65536
#define SM_CN    66560
#define SM_TOT   67584

extern __shared__ char smem_dyn[];

__global__ __launch_bounds__(256, 2)
void hyp_kernel(const float* __restrict__ q,
                const float* __restrict__ k,
                float* __restrict__ out) {
    uint32_t* afrag = (uint32_t*)(smem_dyn + SM_AFRAG);
    uint32_t* bfrag = (uint32_t*)(smem_dyn + SM_BFRAG);
    float2*   qn2s  = (float2*)(smem_dyn + SM_QN);
    float2*   cn2s  = (float2*)(smem_dyn + SM_CN);

    const int tid  = threadIdx.x;
    const int lane = tid & 31;
    const int wid  = tid >> 5;
    const int wm   = wid >> 2;   // 0..1  (M half)
    const int wn   = wid & 3;    // 0..3  (N quarter)
    const int bn = blockIdx.x;   // N tile (0..15)
    const int bm = blockIdx.y;   // M tile (0..15)
    const int bz = blockIdx.z;   // batch

    // ---- Producer: cp.async gmem -> SoA fragment layout (16B granules)
    {
        const float* qb = q + ((size_t)bz * NSEQ + bm * TILE_M) * DDIM;
        const float* kb = k + ((size_t)bz * NSEQ + bn * TILE_N) * DDIM;
        const int j  = tid & 15;       // float4-col index (c0 = 4j)
        const int r0 = tid >> 4;       // 0..15
        const int perm = ((r0 & 7) ^ (j & 7)) << 2;
        // word = (mt*8+s)*128 + p*32 + perm; s=j>>1, p=((r0>>3)&1)|((j&1)<<1)
        const int baseA = (j >> 1) * 128 + (((r0 >> 3) & 1) << 5) + ((j & 1) << 6) + perm;
        const uint32_t a_s = smem_u32(afrag);
        #pragma unroll
        for (int i = 0; i < 8; ++i)
            cp_async16(a_s + 4 * (i * 1024 + baseA),
                       qb + (size_t)(r0 + 16 * i) * DDIM + 4 * j);
        // B: nt = n>>3 = (r0>>3) + 2i; word = nt*512 + s*64 + (j&1)*32 + perm
        const int baseB = (j >> 1) * 64 + ((j & 1) << 5) + perm;
        const uint32_t b_s = smem_u32(bfrag);
        #pragma unroll
        for (int i = 0; i < 8; ++i)
            cp_async16(b_s + 4 * (((r0 >> 3) + 2 * i) * 512 + baseB),
                       kb + (size_t)(r0 + 16 * i) * DDIM + 4 * j);
        asm volatile("cp.async.commit_group;");
    }
    // ---- Norm pairs -> smem
    if (tid < 128) qn2s[tid] = g_qn2[bz * NSEQ + bm * TILE_M + tid];
    else           cn2s[tid - 128] = g_kn2[bz * NSEQ + bn * TILE_N + (tid - 128)];

    asm volatile("cp.async.wait_group 0;");
    __syncthreads();

    // ---- Main MMA loop
    float acc[4][4][4];
    #pragma unroll
    for (int mi = 0; mi < 4; ++mi)
        #pragma unroll
        for (int ni = 0; ni < 4; ++ni)
            #pragma unroll
            for (int r = 0; r < 4; ++r) acc[mi][ni][r] = 0.f;

    const uint32_t* Aw = afrag + wm * 4096;   // wm*4 subtiles * 8 steps * 128
    const uint32_t* Bw = bfrag + wn * 2048;   // wn*4 subtiles * 8 steps * 64

    #pragma unroll
    for (int s = 0; s < 8; ++s) {
        const int x0 = lane ^ (((2 * s) & 7) << 2);       // planes j = 2s
        const int x1 = lane ^ (((2 * s + 1) & 7) << 2);   // planes j = 2s+1
        uint32_t A[4][4];
        uint32_t Bf[4][2];
        #pragma unroll
        for (int mi = 0; mi < 4; ++mi) {
            const uint32_t* p = Aw + mi * 1024 + s * 128;
            A[mi][0] = p[x0];           // (g,   t4)
            A[mi][1] = p[x0 + 32];      // (g+8, t4)
            A[mi][2] = p[x1 + 64];      // (g,   t4+4)
            A[mi][3] = p[x1 + 96];      // (g+8, t4+4)
        }
        #pragma unroll
        for (int ni = 0; ni < 4; ++ni) {
            const uint32_t* p = Bw + ni * 512 + s * 64;
            Bf[ni][0] = p[x0];          // (n, t4)
            Bf[ni][1] = p[x1 + 32];     // (n, t4+4)
        }
        #pragma unroll
        for (int mi = 0; mi < 4; ++mi)
            #pragma unroll
            for (int ni = 0; ni < 4; ++ni)
                mma_tf32_16x8x8(acc[mi][ni], A[mi], Bf[ni]);
    }

    // ---- Epilogue part 1: hyp_dist in-register, stage final values in smem
    const int g  = lane >> 2;
    const int t4 = lane & 3;

    float4 cn[4];   // (kn0, rk0, kn1, rk1) per ni
    #pragma unroll
    for (int ni = 0; ni < 4; ++ni)
        cn[ni] = *(const float4*)&cn2s[wn * 32 + ni * 8 + t4 * 2];

    __syncthreads();   // all fragment reads done; frag smem becomes the stage

    float* stage = (float*)smem_dyn;   // 128 rows x 128 cols, col ^ ((row&7)<<3)

    #pragma unroll
    for (int mi = 0; mi < 4; ++mi) {
        int r0 = wm * 64 + mi * 16 + g;
        float2 qa = qn2s[r0];
        float2 qc = qn2s[r0 + 8];
        const int sw = g << 3;   // (r&7)<<3 == g<<3 for both r0 and r0+8
        #pragma unroll
        for (int ni = 0; ni < 4; ++ni) {
            int c = wn * 32 + ni * 8 + t4 * 2;
            float2 v0, v1;
            v0.x = hyp_dist(acc[mi][ni][0], qa.x + cn[ni].x, qa.y * cn[ni].y);
            v0.y = hyp_dist(acc[mi][ni][1], qa.x + cn[ni].z, qa.y * cn[ni].w);
            v1.x = hyp_dist(acc[mi][ni][2], qc.x + cn[ni].x, qc.y * cn[ni].y);
            v1.y = hyp_dist(acc[mi][ni][3], qc.x + cn[ni].z, qc.y * cn[ni].w);
            *(float2*)&stage[r0 * 128 + (c ^ sw)]       = v0;
            *(float2*)&stage[(r0 + 8) * 128 + (c ^ sw)] = v1;
        }
    }

    __syncthreads();

    // ---- Epilogue part 2: one full output row per warp instruction (coalesced)
    float* ob = out + ((size_t)bz << 22) + (size_t)(bm * TILE_M) * NSEQ + bn * TILE_N;
    #pragma unroll
    for (int ii = 0; ii < 16; ++ii) {
        int row = ii * 8 + wid;
        float4 v = *(float4*)&stage[row * 128 + ((lane * 4) ^ ((row & 7) << 3))];
        *(float4*)(ob + (size_t)row * NSEQ + lane * 4) = v;
    }
}

// ---------------------------------------------------------------------------
// Launch
// ---------------------------------------------------------------------------
extern "C" void kernel_launch(void* const* d_in, const int* in_sizes, int n_in,
                              void* d_out, int out_size) {
    const float* q = (const float*)d_in[0];
    const float* k = (const float*)d_in[1];
    float* out = (float*)d_out;

    norm_kernel<<<(BH * NSEQ) / 256, 256>>>(q, k);

    static int configured = -1;
    if (configured < 0) {
        cudaFuncSetAttribute(hyp_kernel,
                             cudaFuncAttributeMaxDynamicSharedMemorySize, SM_TOT);
        configured = 1;
    }

    dim3 grid(NSEQ / TILE_N, NSEQ / TILE_M, BH);
    hyp_kernel<<<grid, 256, SM_TOT>>>(q, k, out);
}

// round 7
// speedup vs baseline: 1.6298x; 1.6298x over previous
#include <cuda_runtime.h>
#include <cstdint>
#include <cstddef>

// Problem constants (B=4, H=8, N=2048, D=64, c=1)
#define BH   32
#define NSEQ 2048
#define DDIM 64
#define TILE_M 128
#define TILE_N 64

// ---------------------------------------------------------------------------
// Precomputed norms (allocation-free: __device__ globals), interleaved pairs:
//  g_qn2[i] = (||q_i||^2, 2/max(1-||q_i||^2, 1e-3))
//  g_kn2[i] = (||k_i||^2, 1/max(1-||k_i||^2, 1e-3))
// ---------------------------------------------------------------------------
__device__ float2 g_qn2[BH * NSEQ];
__device__ float2 g_kn2[BH * NSEQ];

__global__ void norm_kernel(const float* __restrict__ q, const float* __restrict__ k) {
    int i = blockIdx.x * blockDim.x + threadIdx.x;   // 0 .. BH*NSEQ-1
    const float4* qp = (const float4*)(q + (size_t)i * DDIM);
    const float4* kp = (const float4*)(k + (size_t)i * DDIM);
    float sq = 0.f, sk = 0.f;
    #pragma unroll
    for (int j = 0; j < 16; ++j) {
        float4 a = qp[j];
        sq = fmaf(a.x, a.x, fmaf(a.y, a.y, fmaf(a.z, a.z, fmaf(a.w, a.w, sq))));
        float4 b = kp[j];
        sk = fmaf(b.x, b.x, fmaf(b.y, b.y, fmaf(b.z, b.z, fmaf(b.w, b.w, sk))));
    }
    g_qn2[i] = make_float2(sq, 2.f / fmaxf(1.f - sq, 1e-3f));
    g_kn2[i] = make_float2(sk, 1.f / fmaxf(1.f - sk, 1e-3f));
}

// ---------------------------------------------------------------------------
// Helpers
// ---------------------------------------------------------------------------
// Pack two fp32 into bf16x2 (lo = first arg = lower k index).
__device__ __forceinline__ uint32_t pack_bf16(float lo, float hi) {
    uint32_t r;
    asm("cvt.rn.bf16x2.f32 %0, %1, %2;" : "=r"(r) : "f"(hi), "f"(lo));
    return r;
}

__device__ __forceinline__ void mma_bf16_16x8x16(float* d, const uint32_t* a, const uint32_t* b) {
    asm volatile(
        "mma.sync.aligned.m16n8k16.row.col.f32.bf16.bf16.f32 "
        "{%0,%1,%2,%3}, {%4,%5,%6,%7}, {%8,%9}, {%0,%1,%2,%3};"
        : "+f"(d[0]), "+f"(d[1]), "+f"(d[2]), "+f"(d[3])
        : "r"(a[0]), "r"(a[1]), "r"(a[2]), "r"(a[3]), "r"(b[0]), "r"(b[1]));
}

// acosh(1+t) = log(1 + t + sqrt(t^2+2t)); sqrt.approx(0)=0 so t=0 -> 0 exactly.
__device__ __forceinline__ float hyp_dist(float s, float qnkn, float rr) {
    float diff = fmaf(-2.f, s, qnkn);
    float t = fmaxf(diff, 0.f) * rr;
    float u2 = fmaf(t, t, t + t);
    float u;
    asm("sqrt.approx.f32 %0, %1;" : "=f"(u) : "f"(u2));
    return __logf(1.f + t + u);
}

// ---------------------------------------------------------------------------
// Main kernel: 128x64 output tile per CTA, 128 threads = 4 warps (2M x 2N),
// warp tile 64x32 = 4x4 m16n8k16 (bf16 inputs, fp32 accum).
//
// bf16 fragment layout, per (tile, kstep) block:
//   A block (mt 0..7, ks 0..3): 128 u32 at (mt*4+ks)*128;
//     word = reg*32 + ((lane ^ (ks<<2) ^ (reg<<3)) & 31), regs a0..a3
//   B block (nt 0..7, ks 0..3): 64 u32 at (nt*4+ks)*64; regs b0..b1 same perm.
// Producer: one float4 (row r, cols 4j..4j+3) -> 2 packed bf16x2 -> one
// aligned STS.64 (target lanes l, l+1 are adjacent words). Consumer: permuted
// conflict-free LDS.32.
//
// Staged epilogue: after mainloop the 24KB frag region is dead; hyp_dist is
// applied in-register and final fp32 values staged in smem (32KB, float2 slot
// = c2 ^ (g<<2)), then copied out as full coalesced rows (LDS.128 -> STG.128).
//
// smem (static, 34.5KB): frag A [0:16K), frag B [16K:24K), stage [0:32K)
// (reuse), qn2s [32K:33K), cn2s [33K:33.5K)
// ---------------------------------------------------------------------------
__global__ __launch_bounds__(128, 4)
void hyp_kernel(const float* __restrict__ q,
                const float* __restrict__ k,
                float* __restrict__ out) {
    __shared__ __align__(16) char smem[34816];
    uint32_t* afrag = (uint32_t*)smem;               // 4096 u32
    uint32_t* bfrag = (uint32_t*)(smem + 16384);     // 2048 u32
    float2*   stage = (float2*)smem;                 // 128 x 32 float2
    float2*   qn2s  = (float2*)(smem + 32768);       // 128
    float2*   cn2s  = (float2*)(smem + 33792);       // 64

    const int tid  = threadIdx.x;
    const int lane = tid & 31;
    const int wid  = tid >> 5;
    const int wm   = wid >> 1;   // 0..1  (M half)
    const int wn   = wid & 1;    // 0..1  (N half)
    const int bn = blockIdx.x;   // N tile (0..31)
    const int bm = blockIdx.y;   // M tile (0..15)
    const int bz = blockIdx.z;   // batch

    // ---- Producer: LDG.128 -> pack bf16 -> STS.64 into fragment layout
    {
        const float4* qb = (const float4*)(q + ((size_t)bz * NSEQ + bm * TILE_M) * DDIM);
        const float4* kb = (const float4*)(k + ((size_t)bz * NSEQ + bn * TILE_N) * DDIM);
        const int j   = tid & 15;          // float4-col (c0 = 4j)
        const int r0  = tid >> 4;          // 0..7
        const int ks  = j >> 2;            // k-step 0..3
        const int kh  = (j >> 1) & 1;      // k-high half within step
        const int lb  = (r0 << 2) | ((j & 1) << 1);   // target lane (even)
        // A: 128 rows, r = r0 + 8i, mt = i>>1, row8 = i&1
        #pragma unroll
        for (int i = 0; i < 16; ++i) {
            float4 v = qb[tid + 128 * i];
            const int reg  = (i & 1) | (kh << 1);
            const int slot = (lb ^ (ks << 2) ^ (reg << 3)) & 31;
            uint32_t* w = &afrag[(((i >> 1) * 4 + ks) << 7) + reg * 32 + slot];
            w[0] = pack_bf16(v.x, v.y);
            w[1] = pack_bf16(v.z, v.w);
        }
        // B: 64 rows, r = r0 + 8i, nt = i
        #pragma unroll
        for (int i = 0; i < 8; ++i) {
            float4 v = kb[tid + 128 * i];
            const int reg  = kh;
            const int slot = (lb ^ (ks << 2) ^ (reg << 3)) & 31;
            uint32_t* w = &bfrag[((i * 4 + ks) << 6) + reg * 32 + slot];
            w[0] = pack_bf16(v.x, v.y);
            w[1] = pack_bf16(v.z, v.w);
        }
    }
    // ---- Norm pairs -> smem
    qn2s[tid] = g_qn2[bz * NSEQ + bm * TILE_M + tid];
    if (tid < 64) cn2s[tid] = g_kn2[bz * NSEQ + bn * TILE_N + tid];

    __syncthreads();

    // ---- Main MMA loop: 4 k-steps of k16
    float acc[4][4][4];
    #pragma unroll
    for (int mi = 0; mi < 4; ++mi)
        #pragma unroll
        for (int ni = 0; ni < 4; ++ni)
            #pragma unroll
            for (int r = 0; r < 4; ++r) acc[mi][ni][r] = 0.f;

    #pragma unroll
    for (int s = 0; s < 4; ++s) {
        uint32_t A[4][4];
        uint32_t Bf[4][2];
        #pragma unroll
        for (int mi = 0; mi < 4; ++mi) {
            const uint32_t* blk = afrag + (((wm * 4 + mi) * 4 + s) << 7);
            #pragma unroll
            for (int r = 0; r < 4; ++r)
                A[mi][r] = blk[r * 32 + ((lane ^ (s << 2) ^ (r << 3)) & 31)];
        }
        #pragma unroll
        for (int ni = 0; ni < 4; ++ni) {
            const uint32_t* blk = bfrag + (((wn * 4 + ni) * 4 + s) << 6);
            #pragma unroll
            for (int r = 0; r < 2; ++r)
                Bf[ni][r] = blk[r * 32 + ((lane ^ (s << 2) ^ (r << 3)) & 31)];
        }
        #pragma unroll
        for (int mi = 0; mi < 4; ++mi)
            #pragma unroll
            for (int ni = 0; ni < 4; ++ni)
                mma_bf16_16x8x16(acc[mi][ni], A[mi], Bf[ni]);
    }

    // ---- Epilogue part 1: hyp_dist in-register, stage fp32 in smem
    const int g  = lane >> 2;
    const int t4 = lane & 3;

    float4 cn[4];   // (kn0, rk0, kn1, rk1) per ni
    #pragma unroll
    for (int ni = 0; ni < 4; ++ni)
        cn[ni] = *(const float4*)&cn2s[wn * 32 + ni * 8 + t4 * 2];

    __syncthreads();   // all fragment reads done; frag region becomes stage

    #pragma unroll
    for (int mi = 0; mi < 4; ++mi) {
        int r0 = wm * 64 + mi * 16 + g;
        float2 qa = qn2s[r0];
        float2 qc = qn2s[r0 + 8];
        #pragma unroll
        for (int ni = 0; ni < 4; ++ni) {
            int c2 = (wn * 16 + ni * 4 + t4) ^ (g << 2);   // swizzled float2 slot
            float2 v0, v1;
            v0.x = hyp_dist(acc[mi][ni][0], qa.x + cn[ni].x, qa.y * cn[ni].y);
            v0.y = hyp_dist(acc[mi][ni][1], qa.x + cn[ni].z, qa.y * cn[ni].w);
            v1.x = hyp_dist(acc[mi][ni][2], qc.x + cn[ni].x, qc.y * cn[ni].y);
            v1.y = hyp_dist(acc[mi][ni][3], qc.x + cn[ni].z, qc.y * cn[ni].w);
            stage[r0 * 32 + c2]       = v0;
            stage[(r0 + 8) * 32 + c2] = v1;
        }
    }

    __syncthreads();

    // ---- Epilogue part 2: coalesced row copy (2 rows per warp instruction)
    float* ob = out + ((size_t)bz << 22) + (size_t)(bm * TILE_M) * NSEQ + bn * TILE_N;
    const float4* stage4 = (const float4*)smem;   // 128 rows x 16 float4
    const int f = lane & 15;
    #pragma unroll
    for (int ii = 0; ii < 16; ++ii) {
        int row = wid * 32 + ii * 2 + (lane >> 4);
        float4 v = stage4[row * 16 + (f ^ (((row & 7)) << 1))];
        *(float4*)(ob + (size_t)row * NSEQ + 4 * f) = v;
    }
}

// ---------------------------------------------------------------------------
// Launch
// ---------------------------------------------------------------------------
extern "C" void kernel_launch(void* const* d_in, const int* in_sizes, int n_in,
                              void* d_out, int out_size) {
    const float* q = (const float*)d_in[0];
    const float* k = (const float*)d_in[1];
    float* out = (float*)d_out;

    norm_kernel<<<(BH * NSEQ) / 256, 256>>>(q, k);

    dim3 grid(NSEQ / TILE_N, NSEQ / TILE_M, BH);
    hyp_kernel<<<grid, 128>>>(q, k, out);
}

// round 10
// speedup vs baseline: 1.7051x; 1.0462x over previous
#include <cuda_runtime.h>
#include <cstdint>
#include <cstddef>

// Problem constants (B=4, H=8, N=2048, D=64, c=1)
#define BH   32
#define NSEQ 2048
#define DDIM 64
#define TILE_M 128
#define TILE_N 64

// ---------------------------------------------------------------------------
// Precomputed norms (allocation-free: __device__ globals), interleaved pairs:
//  g_qn2[i] = (||q_i||^2, 2/max(1-||q_i||^2, 1e-3))
//  g_kn2[i] = (||k_i||^2, 1/max(1-||k_i||^2, 1e-3))
// ---------------------------------------------------------------------------
__device__ float2 g_qn2[BH * NSEQ];
__device__ float2 g_kn2[BH * NSEQ];

__global__ void norm_kernel(const float* __restrict__ q, const float* __restrict__ k) {
    int i = blockIdx.x * blockDim.x + threadIdx.x;   // 0 .. BH*NSEQ-1
    const float4* qp = (const float4*)(q + (size_t)i * DDIM);
    const float4* kp = (const float4*)(k + (size_t)i * DDIM);
    float sq = 0.f, sk = 0.f;
    #pragma unroll
    for (int j = 0; j < 16; ++j) {
        float4 a = qp[j];
        sq = fmaf(a.x, a.x, fmaf(a.y, a.y, fmaf(a.z, a.z, fmaf(a.w, a.w, sq))));
        float4 b = kp[j];
        sk = fmaf(b.x, b.x, fmaf(b.y, b.y, fmaf(b.z, b.z, fmaf(b.w, b.w, sk))));
    }
    g_qn2[i] = make_float2(sq, 2.f / fmaxf(1.f - sq, 1e-3f));
    g_kn2[i] = make_float2(sk, 1.f / fmaxf(1.f - sk, 1e-3f));
}

// ---------------------------------------------------------------------------
// Helpers
// ---------------------------------------------------------------------------
__device__ __forceinline__ uint32_t smem_u32(const void* p) {
    uint32_t a;
    asm("{ .reg .u64 t; cvta.to.shared.u64 t, %1; cvt.u32.u64 %0, t; }" : "=r"(a) : "l"(p));
    return a;
}
// Pack two fp32 into bf16x2 (lo = first arg = lower k index).
__device__ __forceinline__ uint32_t pack_bf16(float lo, float hi) {
    uint32_t r;
    asm("cvt.rn.bf16x2.f32 %0, %1, %2;" : "=r"(r) : "f"(hi), "f"(lo));
    return r;
}
__device__ __forceinline__ void ldsm_x4(uint32_t* r, uint32_t addr) {
    asm volatile("ldmatrix.sync.aligned.m8n8.x4.shared.b16 {%0,%1,%2,%3}, [%4];"
                 : "=r"(r[0]), "=r"(r[1]), "=r"(r[2]), "=r"(r[3]) : "r"(addr));
}
__device__ __forceinline__ void mma_bf16_16x8x16(float* d, const uint32_t* a, const uint32_t* b) {
    asm volatile(
        "mma.sync.aligned.m16n8k16.row.col.f32.bf16.bf16.f32 "
        "{%0,%1,%2,%3}, {%4,%5,%6,%7}, {%8,%9}, {%0,%1,%2,%3};"
        : "+f"(d[0]), "+f"(d[1]), "+f"(d[2]), "+f"(d[3])
        : "r"(a[0]), "r"(a[1]), "r"(a[2]), "r"(a[3]), "r"(b[0]), "r"(b[1]));
}

// acosh(1+t) = log(1 + t + sqrt(t^2+2t)); sqrt.approx(0)=0 so t=0 -> 0 exactly.
__device__ __forceinline__ float hyp_dist(float s, float qnkn, float rr) {
    float diff = fmaf(-2.f, s, qnkn);
    float t = fmaxf(diff, 0.f) * rr;
    float u2 = fmaf(t, t, t + t);
    float u;
    asm("sqrt.approx.f32 %0, %1;" : "=f"(u) : "f"(u2));
    return __logf(1.f + t + u);
}

// ---------------------------------------------------------------------------
// Main kernel: 128x64 output tile per CTA, 128 threads = 4 warps (2M x 2N),
// warp tile 64x32 = 4x4 m16n8k16 (bf16 in, fp32 accum).
//
// Tiles stored ROW-MAJOR bf16 (row pitch 128B = 8 x 16B chunks), swizzled:
//   byte addr = row*128 + ((chunk ^ (row&7)) << 4) + sub8
// Producer: float4 -> 2 bf16x2 -> one STS.64, conflict-free (banks
// ((j>>1)^r0)*4 + (j&1)*2 span all 32 per half-warp).
// Mainloop: ldmatrix.x4 (A: 4/step, B: 2/step covering 2 n-tiles) -> 6
// LDS-class instrs + 16 MMA per warp-step (was 24 scalar LDS).
//
// Staged epilogue (round-7): hyp_dist in-register, stage fp32 in smem
// (float2 slot c2 ^ (g<<2)), then coalesced row copy LDS.128 -> STG.128.
//
// smem (static 34KB): A [0:16K), B [16K:24K), stage [0:32K) reuse,
// qn2s [32K:33K), cn2s [33K:33.5K)
// ---------------------------------------------------------------------------
__global__ __launch_bounds__(128, 4)
void hyp_kernel(const float* __restrict__ q,
                const float* __restrict__ k,
                float* __restrict__ out) {
    __shared__ __align__(16) char smem[34816];
    char*   afrag = smem;                        // 128 x 128B
    char*   bfrag = smem + 16384;                // 64 x 128B
    float2* stage = (float2*)smem;               // 128 x 32 float2
    float2* qn2s  = (float2*)(smem + 32768);     // 128
    float2* cn2s  = (float2*)(smem + 33792);     // 64

    const int tid  = threadIdx.x;
    const int lane = tid & 31;
    const int wid  = tid >> 5;
    const int wm   = wid >> 1;   // 0..1  (M half)
    const int wn   = wid & 1;    // 0..1  (N half)
    const int bn = blockIdx.x;   // N tile (0..31)
    const int bm = blockIdx.y;   // M tile (0..15)
    const int bz = blockIdx.z;   // batch

    // ---- Producer: LDG.128 -> pack bf16 -> STS.64 row-major swizzled
    {
        const float4* qb = (const float4*)(q + ((size_t)bz * NSEQ + bm * TILE_M) * DDIM);
        const float4* kb = (const float4*)(k + ((size_t)bz * NSEQ + bn * TILE_N) * DDIM);
        const int j  = tid & 15;       // float4-col (bf16 cols 4j..4j+3)
        const int r0 = tid >> 4;       // 0..7
        const int off = (((j >> 1) ^ r0) << 4) + ((j & 1) << 3);
        #pragma unroll
        for (int i = 0; i < 16; ++i) {            // A rows r0 + 8i
            float4 v = qb[tid + 128 * i];
            uint2 w = make_uint2(pack_bf16(v.x, v.y), pack_bf16(v.z, v.w));
            *(uint2*)(afrag + (r0 + 8 * i) * 128 + off) = w;
        }
        #pragma unroll
        for (int i = 0; i < 8; ++i) {             // B rows r0 + 8i
            float4 v = kb[tid + 128 * i];
            uint2 w = make_uint2(pack_bf16(v.x, v.y), pack_bf16(v.z, v.w));
            *(uint2*)(bfrag + (r0 + 8 * i) * 128 + off) = w;
        }
    }
    // ---- Norm pairs -> smem
    qn2s[tid] = g_qn2[bz * NSEQ + bm * TILE_M + tid];
    if (tid < 64) cn2s[tid] = g_kn2[bz * NSEQ + bn * TILE_N + tid];

    __syncthreads();

    // ---- Main MMA loop: 4 k-steps of k16, ldmatrix operand loads
    float acc[4][4][4];
    #pragma unroll
    for (int mi = 0; mi < 4; ++mi)
        #pragma unroll
        for (int ni = 0; ni < 4; ++ni)
            #pragma unroll
            for (int r = 0; r < 4; ++r) acc[mi][ni][r] = 0.f;

    // Per-lane ldmatrix row addresses (chunk offset added per step).
    const int grp = lane >> 3;        // 0..3
    const int rl  = lane & 7;
    // A: matrices {a0,a1,a2,a3}: row sub = (grp&1)*8 + rl, chunk bit = grp>>1
    const uint32_t a_rowaddr = smem_u32(afrag) +
        (wm * 64 + ((grp & 1) << 3) + rl) * 128;
    const int abit = grp >> 1;
    // B: matrices {b0(ni),b1(ni),b0(ni+1),b1(ni+1)}: row sub = (grp>>1)*8 + rl,
    // chunk bit = grp&1
    const uint32_t b_rowaddr = smem_u32(bfrag) +
        (wn * 32 + ((grp >> 1) << 3) + rl) * 128;
    const int bbit = grp & 1;

    #pragma unroll
    for (int s = 0; s < 4; ++s) {
        const uint32_t aoff = (uint32_t)(((2 * s + abit) ^ rl) << 4);
        const uint32_t boff = (uint32_t)(((2 * s + bbit) ^ rl) << 4);
        uint32_t A[4][4];
        uint32_t Bf[4][2];
        #pragma unroll
        for (int mi = 0; mi < 4; ++mi)
            ldsm_x4(A[mi], a_rowaddr + mi * (16 * 128) + aoff);
        ldsm_x4(&Bf[0][0], b_rowaddr + boff);                  // ni 0,1
        ldsm_x4(&Bf[2][0], b_rowaddr + (16 * 128) + boff);     // ni 2,3
        #pragma unroll
        for (int mi = 0; mi < 4; ++mi)
            #pragma unroll
            for (int ni = 0; ni < 4; ++ni)
                mma_bf16_16x8x16(acc[mi][ni], A[mi], Bf[ni]);
    }

    // ---- Epilogue part 1: hyp_dist in-register, stage fp32 in smem
    const int g  = lane >> 2;
    const int t4 = lane & 3;

    float4 cn[4];   // (kn0, rk0, kn1, rk1) per ni
    #pragma unroll
    for (int ni = 0; ni < 4; ++ni)
        cn[ni] = *(const float4*)&cn2s[wn * 32 + ni * 8 + t4 * 2];

    __syncthreads();   // all fragment reads done; frag region becomes stage

    #pragma unroll
    for (int mi = 0; mi < 4; ++mi) {
        int r0 = wm * 64 + mi * 16 + g;
        float2 qa = qn2s[r0];
        float2 qc = qn2s[r0 + 8];
        #pragma unroll
        for (int ni = 0; ni < 4; ++ni) {
            int c2 = (wn * 16 + ni * 4 + t4) ^ (g << 2);   // swizzled float2 slot
            float2 v0, v1;
            v0.x = hyp_dist(acc[mi][ni][0], qa.x + cn[ni].x, qa.y * cn[ni].y);
            v0.y = hyp_dist(acc[mi][ni][1], qa.x + cn[ni].z, qa.y * cn[ni].w);
            v1.x = hyp_dist(acc[mi][ni][2], qc.x + cn[ni].x, qc.y * cn[ni].y);
            v1.y = hyp_dist(acc[mi][ni][3], qc.x + cn[ni].z, qc.y * cn[ni].w);
            stage[r0 * 32 + c2]       = v0;
            stage[(r0 + 8) * 32 + c2] = v1;
        }
    }

    __syncthreads();

    // ---- Epilogue part 2: coalesced row copy (2 rows per warp instruction)
    float* ob = out + ((size_t)bz << 22) + (size_t)(bm * TILE_M) * NSEQ + bn * TILE_N;
    const float4* stage4 = (const float4*)smem;   // 128 rows x 16 float4
    const int f = lane & 15;
    #pragma unroll
    for (int ii = 0; ii < 16; ++ii) {
        int row = wid * 32 + ii * 2 + (lane >> 4);
        float4 v = stage4[row * 16 + (f ^ (((row & 7)) << 1))];
        *(float4*)(ob + (size_t)row * NSEQ + 4 * f) = v;
    }
}

// ---------------------------------------------------------------------------
// Launch
// ---------------------------------------------------------------------------
extern "C" void kernel_launch(void* const* d_in, const int* in_sizes, int n_in,
                              void* d_out, int out_size) {
    const float* q = (const float*)d_in[0];
    const float* k = (const float*)d_in[1];
    float* out = (float*)d_out;

    norm_kernel<<<(BH * NSEQ) / 256, 256>>>(q, k);

    dim3 grid(NSEQ / TILE_N, NSEQ / TILE_M, BH);
    hyp_kernel<<<grid, 128>>>(q, k, out);
}

// round 11
// speedup vs baseline: 1.7987x; 1.0549x over previous
#include <cuda_runtime.h>
#include <cstdint>
#include <cstddef>

// Problem constants (B=4, H=8, N=2048, D=64, c=1)
#define BH   32
#define NSEQ 2048
#define DDIM 64
#define TILE_M 128
#define TILE_N 64

// ---------------------------------------------------------------------------
// Precomputed norms (allocation-free: __device__ globals), interleaved pairs:
//  g_qn2[i] = (||q_i||^2, 2/max(1-||q_i||^2, 1e-3))
//  g_kn2[i] = (||k_i||^2, 1/max(1-||k_i||^2, 1e-3))
// ---------------------------------------------------------------------------
__device__ float2 g_qn2[BH * NSEQ];
__device__ float2 g_kn2[BH * NSEQ];

__global__ void norm_kernel(const float* __restrict__ q, const float* __restrict__ k) {
    int i = blockIdx.x * blockDim.x + threadIdx.x;   // 0 .. BH*NSEQ-1
    const float4* qp = (const float4*)(q + (size_t)i * DDIM);
    const float4* kp = (const float4*)(k + (size_t)i * DDIM);
    float sq = 0.f, sk = 0.f;
    #pragma unroll
    for (int j = 0; j < 16; ++j) {
        float4 a = qp[j];
        sq = fmaf(a.x, a.x, fmaf(a.y, a.y, fmaf(a.z, a.z, fmaf(a.w, a.w, sq))));
        float4 b = kp[j];
        sk = fmaf(b.x, b.x, fmaf(b.y, b.y, fmaf(b.z, b.z, fmaf(b.w, b.w, sk))));
    }
    g_qn2[i] = make_float2(sq, 2.f / fmaxf(1.f - sq, 1e-3f));
    g_kn2[i] = make_float2(sk, 1.f / fmaxf(1.f - sk, 1e-3f));
}

// ---------------------------------------------------------------------------
// Helpers
// ---------------------------------------------------------------------------
__device__ __forceinline__ uint32_t smem_u32(const void* p) {
    uint32_t a;
    asm("{ .reg .u64 t; cvta.to.shared.u64 t, %1; cvt.u32.u64 %0, t; }" : "=r"(a) : "l"(p));
    return a;
}
// Pack two fp32 into bf16x2 (lo = first arg = lower k index).
__device__ __forceinline__ uint32_t pack_bf16(float lo, float hi) {
    uint32_t r;
    asm("cvt.rn.bf16x2.f32 %0, %1, %2;" : "=r"(r) : "f"(hi), "f"(lo));
    return r;
}
__device__ __forceinline__ void ldsm_x4(uint32_t* r, uint32_t addr) {
    asm volatile("ldmatrix.sync.aligned.m8n8.x4.shared.b16 {%0,%1,%2,%3}, [%4];"
                 : "=r"(r[0]), "=r"(r[1]), "=r"(r[2]), "=r"(r[3]) : "r"(addr));
}
__device__ __forceinline__ void mma_bf16_16x8x16(float* d, const uint32_t* a, const uint32_t* b) {
    asm volatile(
        "mma.sync.aligned.m16n8k16.row.col.f32.bf16.bf16.f32 "
        "{%0,%1,%2,%3}, {%4,%5,%6,%7}, {%8,%9}, {%0,%1,%2,%3};"
        : "+f"(d[0]), "+f"(d[1]), "+f"(d[2]), "+f"(d[3])
        : "r"(a[0]), "r"(a[1]), "r"(a[2]), "r"(a[3]), "r"(b[0]), "r"(b[1]));
}

// acosh(z) with z = 1 + max(diff,0)*rr, computed as log(z + sqrt(z^2-1)).
// z >= 1 always (fma with +1); z==1 -> u2 = fma(1,1,-1) = 0 exactly -> d = 0.
// Cancellation in z^2-1 only matters for diff ~ 0, which concentration of
// 64-dim Gaussian distances makes negligible in aggregate.
__device__ __forceinline__ float hyp_dist(float s, float qnkn, float rr) {
    float diff = fmaf(-2.f, s, qnkn);
    float z = fmaf(fmaxf(diff, 0.f), rr, 1.f);
    float u2 = fmaf(z, z, -1.f);
    float u;
    asm("sqrt.approx.f32 %0, %1;" : "=f"(u) : "f"(u2));
    return __logf(z + u);
}

// ---------------------------------------------------------------------------
// Main kernel: 128x64 output tile per CTA, 128 threads = 4 warps (2M x 2N),
// warp tile 64x32 = 4x4 m16n8k16 (bf16 in, fp32 accum). 5 CTAs/SM.
//
// Tiles stored ROW-MAJOR bf16 (row pitch 128B = 8 x 16B chunks), swizzled:
//   byte addr = row*128 + ((chunk ^ (row&7)) << 4) + sub8
// Producer: float4 -> 2 bf16x2 -> one STS.64, conflict-free.
// Mainloop: per k-step load B (2 ldmatrix.x4), then per mi: 1 ldmatrix.x4 A
// followed by its 4 MMAs (keeps live registers ~92 so 5 CTAs/SM fit).
//
// Staged epilogue: hyp_dist in-register, stage fp32 in smem (float2 slot
// c2 ^ (g<<2)), then coalesced row copy LDS.128 -> STG.128.
//
// smem (static 34KB): A [0:16K), B [16K:24K), stage [0:32K) reuse,
// qn2s [32K:33K), cn2s [33K:33.5K)
// ---------------------------------------------------------------------------
__global__ __launch_bounds__(128, 5)
void hyp_kernel(const float* __restrict__ q,
                const float* __restrict__ k,
                float* __restrict__ out) {
    __shared__ __align__(16) char smem[34816];
    char*   afrag = smem;                        // 128 x 128B
    char*   bfrag = smem + 16384;                // 64 x 128B
    float2* stage = (float2*)smem;               // 128 x 32 float2
    float2* qn2s  = (float2*)(smem + 32768);     // 128
    float2* cn2s  = (float2*)(smem + 33792);     // 64

    const int tid  = threadIdx.x;
    const int lane = tid & 31;
    const int wid  = tid >> 5;
    const int wm   = wid >> 1;   // 0..1  (M half)
    const int wn   = wid & 1;    // 0..1  (N half)
    const int bn = blockIdx.x;   // N tile (0..31)
    const int bm = blockIdx.y;   // M tile (0..15)
    const int bz = blockIdx.z;   // batch

    // ---- Producer: LDG.128 -> pack bf16 -> STS.64 row-major swizzled
    {
        const float4* qb = (const float4*)(q + ((size_t)bz * NSEQ + bm * TILE_M) * DDIM);
        const float4* kb = (const float4*)(k + ((size_t)bz * NSEQ + bn * TILE_N) * DDIM);
        const int j  = tid & 15;       // float4-col (bf16 cols 4j..4j+3)
        const int r0 = tid >> 4;       // 0..7
        const int off = (((j >> 1) ^ r0) << 4) + ((j & 1) << 3);
        #pragma unroll
        for (int i = 0; i < 16; ++i) {            // A rows r0 + 8i
            float4 v = qb[tid + 128 * i];
            uint2 w = make_uint2(pack_bf16(v.x, v.y), pack_bf16(v.z, v.w));
            *(uint2*)(afrag + (r0 + 8 * i) * 128 + off) = w;
        }
        #pragma unroll
        for (int i = 0; i < 8; ++i) {             // B rows r0 + 8i
            float4 v = kb[tid + 128 * i];
            uint2 w = make_uint2(pack_bf16(v.x, v.y), pack_bf16(v.z, v.w));
            *(uint2*)(bfrag + (r0 + 8 * i) * 128 + off) = w;
        }
    }
    // ---- Norm pairs -> smem
    qn2s[tid] = g_qn2[bz * NSEQ + bm * TILE_M + tid];
    if (tid < 64) cn2s[tid] = g_kn2[bz * NSEQ + bn * TILE_N + tid];

    __syncthreads();

    // ---- Main MMA loop: 4 k-steps of k16, ldmatrix operand loads
    float acc[4][4][4];
    #pragma unroll
    for (int mi = 0; mi < 4; ++mi)
        #pragma unroll
        for (int ni = 0; ni < 4; ++ni)
            #pragma unroll
            for (int r = 0; r < 4; ++r) acc[mi][ni][r] = 0.f;

    // Per-lane ldmatrix row addresses (chunk offset added per step).
    const int grp = lane >> 3;        // 0..3
    const int rl  = lane & 7;
    // A: matrices {a0,a1,a2,a3}: row sub = (grp&1)*8 + rl, chunk bit = grp>>1
    const uint32_t a_rowaddr = smem_u32(afrag) +
        (wm * 64 + ((grp & 1) << 3) + rl) * 128;
    const int abit = grp >> 1;
    // B: matrices {b0(ni),b1(ni),b0(ni+1),b1(ni+1)}: row sub = (grp>>1)*8 + rl,
    // chunk bit = grp&1
    const uint32_t b_rowaddr = smem_u32(bfrag) +
        (wn * 32 + ((grp >> 1) << 3) + rl) * 128;
    const int bbit = grp & 1;

    #pragma unroll
    for (int s = 0; s < 4; ++s) {
        const uint32_t aoff = (uint32_t)(((2 * s + abit) ^ rl) << 4);
        const uint32_t boff = (uint32_t)(((2 * s + bbit) ^ rl) << 4);
        uint32_t Bf[4][2];
        ldsm_x4(&Bf[0][0], b_rowaddr + boff);                  // ni 0,1
        ldsm_x4(&Bf[2][0], b_rowaddr + (16 * 128) + boff);     // ni 2,3
        #pragma unroll
        for (int mi = 0; mi < 4; ++mi) {
            uint32_t A[4];
            ldsm_x4(A, a_rowaddr + mi * (16 * 128) + aoff);
            #pragma unroll
            for (int ni = 0; ni < 4; ++ni)
                mma_bf16_16x8x16(acc[mi][ni], A, Bf[ni]);
        }
    }

    // ---- Epilogue part 1: hyp_dist in-register, stage fp32 in smem
    const int g  = lane >> 2;
    const int t4 = lane & 3;

    float4 cn[4];   // (kn0, rk0, kn1, rk1) per ni
    #pragma unroll
    for (int ni = 0; ni < 4; ++ni)
        cn[ni] = *(const float4*)&cn2s[wn * 32 + ni * 8 + t4 * 2];

    __syncthreads();   // all fragment reads done; frag region becomes stage

    #pragma unroll
    for (int mi = 0; mi < 4; ++mi) {
        int r0 = wm * 64 + mi * 16 + g;
        float2 qa = qn2s[r0];
        float2 qc = qn2s[r0 + 8];
        #pragma unroll
        for (int ni = 0; ni < 4; ++ni) {
            int c2 = (wn * 16 + ni * 4 + t4) ^ (g << 2);   // swizzled float2 slot
            float2 v0, v1;
            v0.x = hyp_dist(acc[mi][ni][0], qa.x + cn[ni].x, qa.y * cn[ni].y);
            v0.y = hyp_dist(acc[mi][ni][1], qa.x + cn[ni].z, qa.y * cn[ni].w);
            v1.x = hyp_dist(acc[mi][ni][2], qc.x + cn[ni].x, qc.y * cn[ni].y);
            v1.y = hyp_dist(acc[mi][ni][3], qc.x + cn[ni].z, qc.y * cn[ni].w);
            stage[r0 * 32 + c2]       = v0;
            stage[(r0 + 8) * 32 + c2] = v1;
        }
    }

    __syncthreads();

    // ---- Epilogue part 2: coalesced row copy (2 rows per warp instruction)
    float* ob = out + ((size_t)bz << 22) + (size_t)(bm * TILE_M) * NSEQ + bn * TILE_N;
    const float4* stage4 = (const float4*)smem;   // 128 rows x 16 float4
    const int f = lane & 15;
    #pragma unroll
    for (int ii = 0; ii < 16; ++ii) {
        int row = wid * 32 + ii * 2 + (lane >> 4);
        float4 v = stage4[row * 16 + (f ^ (((row & 7)) << 1))];
        *(float4*)(ob + (size_t)row * NSEQ + 4 * f) = v;
    }
}

// ---------------------------------------------------------------------------
// Launch
// ---------------------------------------------------------------------------
extern "C" void kernel_launch(void* const* d_in, const int* in_sizes, int n_in,
                              void* d_out, int out_size) {
    const float* q = (const float*)d_in[0];
    const float* k = (const float*)d_in[1];
    float* out = (float*)d_out;

    norm_kernel<<<(BH * NSEQ) / 256, 256>>>(q, k);

    dim3 grid(NSEQ / TILE_N, NSEQ / TILE_M, BH);
    hyp_kernel<<<grid, 128>>>(q, k, out);
}